// round 16
// baseline (speedup 1.0000x reference)
#include <cuda_runtime.h>
#include <math.h>

#define B_  512
#define T_  512
#define H_  100
#define DI_ 101
#define DO_ 2

typedef unsigned long long ull;

__device__ float g_xp[(size_t)B_ * T_ * H_];   // holds 0.1*(inp@Wx^T + b)

__device__ __forceinline__ ull fma2(ull a, ull b, ull c) {
    ull d;
    asm("fma.rn.f32x2 %0, %1, %2, %3;" : "=l"(d) : "l"(a), "l"(b), "l"(c));
    return d;
}
__device__ __forceinline__ ull add2(ull a, ull b) {
    ull d;
    asm("add.rn.f32x2 %0, %1, %2;" : "=l"(d) : "l"(a), "l"(b));
    return d;
}
__device__ __forceinline__ ull dup2(float a) {
    ull d;
    asm("mov.b64 %0, {%1, %1};" : "=l"(d) : "f"(a));
    return d;
}
__device__ __forceinline__ ull pack2(float lo, float hi) {
    ull d;
    asm("mov.b64 %0, {%1, %2};" : "=l"(d) : "f"(lo), "f"(hi));
    return d;
}
__device__ __forceinline__ float2 u2f(ull v) {
    float2 f;
    asm("mov.b64 {%0, %1}, %2;" : "=f"(f.x), "=f"(f.y) : "l"(v));
    return f;
}

// ---------------------------------------------------------------------------
// Kernel A: g_xp[r][j] = 0.1*(sum_i input[r][i]*Wx[j][i] + b[j])
// EXACT round-7 kernel (measured 163.9-165.2us; at scalar FFMA2 floor).
// ---------------------------------------------------------------------------
#define INS_STRIDE 68
__global__ void __launch_bounds__(256, 3) xp_gemm_kernel(
    const float* __restrict__ inp,   // [B*T, DI]
    const float* __restrict__ Wx,    // [H, DI]
    const float* __restrict__ bias)  // [H]
{
    extern __shared__ __align__(16) float smem[];
    float* Wx_s = smem;                 // [i][j]  (pre-scaled by 0.1)
    float* in_s = smem + DI_ * H_;      // [i][r]

    const int tid = threadIdx.x;
    const int tx  = tid & 31;   // col quad (active tx < 25)
    const int ty  = tid >> 5;   // warp id (0..7) -> rows 8*ty..8*ty+7

    for (int idx = tid; idx < DI_ * H_; idx += 256) {
        int j = idx / DI_;
        int i = idx - j * DI_;
        Wx_s[i * H_ + j] = 0.1f * Wx[idx];
    }

    float bv[4] = {0.f, 0.f, 0.f, 0.f};
    if (tx < 25) {
#pragma unroll
        for (int c = 0; c < 4; c++) bv[c] = 0.1f * bias[4 * tx + c];
    }

    const int ntiles = (B_ * T_) / 64;   // 4096
    for (int tile = blockIdx.x; tile < ntiles; tile += gridDim.x) {
        __syncthreads();
        const int rbase = tile * 64;
        for (int idx = tid; idx < 64 * DI_; idx += 256) {
            int r = idx / DI_;
            int i = idx - r * DI_;
            in_s[i * INS_STRIDE + r] = inp[(size_t)(rbase + r) * DI_ + i];
        }
        __syncthreads();

        if (tx < 25) {
            ull acc[4][4];
#pragma unroll
            for (int p = 0; p < 4; p++)
#pragma unroll
                for (int c = 0; c < 4; c++) acc[p][c] = dup2(bv[c]);

#pragma unroll 4
            for (int i = 0; i < DI_; i++) {
                ulonglong2 ap0 = *(const ulonglong2*)(in_s + i * INS_STRIDE + 8 * ty);
                ulonglong2 ap1 = *(const ulonglong2*)(in_s + i * INS_STRIDE + 8 * ty + 4);
                float4 wv = *(const float4*)(Wx_s + i * H_ + 4 * tx);
                ull w0 = dup2(wv.x), w1 = dup2(wv.y), w2 = dup2(wv.z), w3 = dup2(wv.w);
                acc[0][0] = fma2(ap0.x, w0, acc[0][0]);
                acc[0][1] = fma2(ap0.x, w1, acc[0][1]);
                acc[0][2] = fma2(ap0.x, w2, acc[0][2]);
                acc[0][3] = fma2(ap0.x, w3, acc[0][3]);
                acc[1][0] = fma2(ap0.y, w0, acc[1][0]);
                acc[1][1] = fma2(ap0.y, w1, acc[1][1]);
                acc[1][2] = fma2(ap0.y, w2, acc[1][2]);
                acc[1][3] = fma2(ap0.y, w3, acc[1][3]);
                acc[2][0] = fma2(ap1.x, w0, acc[2][0]);
                acc[2][1] = fma2(ap1.x, w1, acc[2][1]);
                acc[2][2] = fma2(ap1.x, w2, acc[2][2]);
                acc[2][3] = fma2(ap1.x, w3, acc[2][3]);
                acc[3][0] = fma2(ap1.y, w0, acc[3][0]);
                acc[3][1] = fma2(ap1.y, w1, acc[3][1]);
                acc[3][2] = fma2(ap1.y, w2, acc[3][2]);
                acc[3][3] = fma2(ap1.y, w3, acc[3][3]);
            }
#pragma unroll
            for (int p = 0; p < 4; p++) {
                float2 c0 = u2f(acc[p][0]);
                float2 c1 = u2f(acc[p][1]);
                float2 c2 = u2f(acc[p][2]);
                float2 c3 = u2f(acc[p][3]);
                int re = rbase + 8 * ty + 2 * p;
                float4 oe; oe.x = c0.x; oe.y = c1.x; oe.z = c2.x; oe.w = c3.x;
                float4 oo; oo.x = c0.y; oo.y = c1.y; oo.z = c2.y; oo.w = c3.y;
                *(float4*)(g_xp + (size_t)re * H_ + 4 * tx)       = oe;
                *(float4*)(g_xp + (size_t)(re + 1) * H_ + 4 * tx) = oo;
            }
        }
    }
}

// ---------------------------------------------------------------------------
// Kernel B: sequential scan — round-15 structure (2 warps/chain, 2 rows/thread,
// 64-thread named barriers, occ 2). Changes: stagger removed (ablation),
// branch-free prefetch via clamped index.
// ---------------------------------------------------------------------------
__global__ void __launch_bounds__(128, 2) scan_kernel(
    const float* __restrict__ noise,   // [B, T, H]
    const float* __restrict__ Wh,      // [H, H]
    const float* __restrict__ ah0,     // [H]
    float* __restrict__ hstore)        // [B, T, H]
{
    __shared__ __align__(16) float hs[2][2][104];   // [pair][buf][k]

    const int tid  = threadIdx.x;
    const int lane = tid & 31;
    const int wp   = (tid >> 5) & 1;    // warp within pair
    const int pair = tid >> 6;          // 0 or 1
    const bool act = lane < 25;
    const int j0   = 50 * wp + lane;
    const int j1   = j0 + 25;
    const int chain = blockIdx.x * 2 + pair;
    const int barid = pair + 1;         // named barriers 1 and 2

    // 0.1*W rows j0, j1 packed over k (k-pairs)
    ull wk0[50], wk1[50];
    if (act) {
        const float2* w0 = (const float2*)(Wh + j0 * H_);
        const float2* w1 = (const float2*)(Wh + j1 * H_);
#pragma unroll
        for (int kk = 0; kk < 50; kk++) {
            float2 a = w0[kk];
            float2 b = w1[kk];
            wk0[kk] = pack2(0.1f * a.x, 0.1f * a.y);
            wk1[kk] = pack2(0.1f * b.x, 0.1f * b.y);
        }
    }

    float ahx = 0.f, ahy = 0.f;
    if (act) {
        ahx = ah0[j0];
        ahy = ah0[j1];
        hs[pair][0][j0] = tanhf(fmaxf(ahx, 0.f));
        hs[pair][0][j1] = tanhf(fmaxf(ahy, 0.f));
    }

    const size_t base = (size_t)chain * (T_ * H_);
    const float* xps = g_xp  + base + j0;    // row j1 = +25
    const float* nzs = noise + base + j0;
    float*       hst = hstore + base + j0;

    // depth-2 register prefetch ring
    float xc0 = 0.f, xc1 = 0.f, nc0 = 0.f, nc1 = 0.f;   // step t
    float xn0 = 0.f, xn1 = 0.f, nn0 = 0.f, nn1 = 0.f;   // step t+1
    if (act) {
        xc0 = xps[0];       xc1 = xps[25];
        nc0 = nzs[0];       nc1 = nzs[25];
        xn0 = xps[H_];      xn1 = xps[H_ + 25];
        nn0 = nzs[H_];      nn1 = nzs[H_ + 25];
    }
    __syncthreads();   // covers hs init for both pairs

    int buf = 0;
    for (int t = 0; t < T_; t++) {
        // prefetch t+2 (clamped; branch-free — re-reads last row at the end)
        float p0 = 0.f, p1 = 0.f, q0 = 0.f, q1 = 0.f;
        {
            int tc = (t + 2 < T_) ? (t + 2) : (T_ - 1);
            size_t o = (size_t)tc * H_;
            if (act) {
                p0 = xps[o];  p1 = xps[o + 25];
                q0 = nzs[o];  q1 = nzs[o + 25];
            }
        }

        if (act) {
            const ulonglong2* h4 = (const ulonglong2*)hs[pair][buf];
            ull a0 = 0, b0 = 0, a1 = 0, b1 = 0;
#pragma unroll
            for (int kk = 0; kk < 25; kk++) {
                ulonglong2 v = h4[kk];            // k = 4kk .. 4kk+3
                a0 = fma2(v.x, wk0[2 * kk],     a0);
                b0 = fma2(v.y, wk0[2 * kk + 1], b0);
                a1 = fma2(v.x, wk1[2 * kk],     a1);
                b1 = fma2(v.y, wk1[2 * kk + 1], b1);
            }
            float2 s0 = u2f(add2(a0, b0));
            float2 s1 = u2f(add2(a1, b1));
            float sum0 = s0.x + s0.y;
            float sum1 = s1.x + s1.y;

            ahx = fmaf(0.9f, ahx, sum0 + xc0);
            ahy = fmaf(0.9f, ahy, sum1 + xc1);
            float x0 = fmaxf(ahx, 0.f);
            float x1 = fmaxf(ahy, 0.f);
            float e0 = __expf(-2.f * x0);
            float e1 = __expf(-2.f * x1);
            float h0 = __fdividef(1.f - e0, 1.f + e0) + nc0;
            float h1 = __fdividef(1.f - e1, 1.f + e1) + nc1;

            hs[pair][buf ^ 1][j0] = h0;
            hs[pair][buf ^ 1][j1] = h1;
            size_t o = (size_t)t * H_;
            hst[o]      = h0;
            hst[o + 25] = h1;
        }
        // rotate ring
        xc0 = xn0; xc1 = xn1; nc0 = nn0; nc1 = nn1;
        xn0 = p0;  xn1 = p1;  nn0 = q0;  nn1 = q1;
        buf ^= 1;
        asm volatile("bar.sync %0, %1;" :: "r"(barid), "r"(64) : "memory");
    }
}

// ---------------------------------------------------------------------------
// Kernel C: outproj, THREAD-PER-ROW, 512-thread blocks, streaming loads.
// ---------------------------------------------------------------------------
__global__ void __launch_bounds__(512) outproj_kernel(
    const float* __restrict__ hst,   // [B*T, H]
    const float* __restrict__ Wy,    // [DO, H]
    float* __restrict__ out)         // [B*T, DO]
{
    __shared__ ull wy2[H_];
    const int tid = threadIdx.x;
    if (tid < H_) wy2[tid] = pack2(Wy[tid], Wy[H_ + tid]);
    __syncthreads();

    const size_t row = (size_t)blockIdx.x * 512 + tid;
    const float4* rp = (const float4*)(hst + row * H_);   // 400B rows, 16B aligned

    ull acc0 = 0, acc1 = 0, acc2 = 0, acc3 = 0;
#pragma unroll
    for (int q = 0; q < 25; q++) {
        float4 v = __ldcs(rp + q);          // streaming: evict-first
        acc0 = fma2(dup2(v.x), wy2[4 * q + 0], acc0);
        acc1 = fma2(dup2(v.y), wy2[4 * q + 1], acc1);
        acc2 = fma2(dup2(v.z), wy2[4 * q + 2], acc2);
        acc3 = fma2(dup2(v.w), wy2[4 * q + 3], acc3);
    }
    ull r = add2(add2(acc0, acc1), add2(acc2, acc3));
    *(ull*)(out + row * DO_) = r;
}

// ---------------------------------------------------------------------------
extern "C" void kernel_launch(void* const* d_in, const int* in_sizes, int n_in,
                              void* d_out, int out_size)
{
    const float* inp   = (const float*)d_in[0];  // [B,T,DI]
    const float* noise = (const float*)d_in[1];  // [B,T,H]
    const float* Wx    = (const float*)d_in[2];  // [H,DI]
    const float* bias  = (const float*)d_in[3];  // [H]
    const float* Wh    = (const float*)d_in[4];  // [H,H]
    const float* Wy    = (const float*)d_in[5];  // [DO,H]
    const float* ah0   = (const float*)d_in[6];  // [H]

    float* out    = (float*)d_out;                  // [B,T,DO] first
    float* hstore = out + (size_t)B_ * T_ * DO_;    // [B,T,H] second

    const int xp_smem = (DI_ * H_ + DI_ * INS_STRIDE) * (int)sizeof(float);  // 67872 B
    static int attr_done = 0;
    if (!attr_done) {
        cudaFuncSetAttribute(xp_gemm_kernel,
                             cudaFuncAttributeMaxDynamicSharedMemorySize, xp_smem);
        cudaFuncSetAttribute(xp_gemm_kernel,
                             cudaFuncAttributePreferredSharedMemoryCarveout,
                             cudaSharedmemCarveoutMaxShared);
        attr_done = 1;
    }

    xp_gemm_kernel<<<1024, 256, xp_smem>>>(inp, Wx, bias);
    scan_kernel<<<B_ / 2, 128>>>(noise, Wh, ah0, hstore);
    outproj_kernel<<<(B_ * T_) / 512, 512>>>(hstore, Wy, out);
}

// round 17
// speedup vs baseline: 1.0730x; 1.0730x over previous
#include <cuda_runtime.h>
#include <math.h>

#define B_  512
#define T_  512
#define H_  100
#define DI_ 101
#define DO_ 2

typedef unsigned long long ull;

__device__ float g_xp[(size_t)B_ * T_ * H_];   // holds 0.1*(inp@Wx^T + b)

__device__ __forceinline__ ull fma2(ull a, ull b, ull c) {
    ull d;
    asm("fma.rn.f32x2 %0, %1, %2, %3;" : "=l"(d) : "l"(a), "l"(b), "l"(c));
    return d;
}
__device__ __forceinline__ ull add2(ull a, ull b) {
    ull d;
    asm("add.rn.f32x2 %0, %1, %2;" : "=l"(d) : "l"(a), "l"(b));
    return d;
}
__device__ __forceinline__ ull dup2(float a) {
    ull d;
    asm("mov.b64 %0, {%1, %1};" : "=l"(d) : "f"(a));
    return d;
}
__device__ __forceinline__ ull pack2(float lo, float hi) {
    ull d;
    asm("mov.b64 %0, {%1, %2};" : "=l"(d) : "f"(lo), "f"(hi));
    return d;
}
__device__ __forceinline__ float2 u2f(ull v) {
    float2 f;
    asm("mov.b64 {%0, %1}, %2;" : "=f"(f.x), "=f"(f.y) : "l"(v));
    return f;
}

// ---------------------------------------------------------------------------
// Kernel A: g_xp[r][j] = 0.1*(sum_i input[r][i]*Wx[j][i] + b[j])
// EXACT round-7 kernel (measured 163.9-165.2us; at scalar FFMA2 floor).
// ---------------------------------------------------------------------------
#define INS_STRIDE 68
__global__ void __launch_bounds__(256, 3) xp_gemm_kernel(
    const float* __restrict__ inp,   // [B*T, DI]
    const float* __restrict__ Wx,    // [H, DI]
    const float* __restrict__ bias)  // [H]
{
    extern __shared__ __align__(16) float smem[];
    float* Wx_s = smem;                 // [i][j]  (pre-scaled by 0.1)
    float* in_s = smem + DI_ * H_;      // [i][r]

    const int tid = threadIdx.x;
    const int tx  = tid & 31;   // col quad (active tx < 25)
    const int ty  = tid >> 5;   // warp id (0..7) -> rows 8*ty..8*ty+7

    for (int idx = tid; idx < DI_ * H_; idx += 256) {
        int j = idx / DI_;
        int i = idx - j * DI_;
        Wx_s[i * H_ + j] = 0.1f * Wx[idx];
    }

    float bv[4] = {0.f, 0.f, 0.f, 0.f};
    if (tx < 25) {
#pragma unroll
        for (int c = 0; c < 4; c++) bv[c] = 0.1f * bias[4 * tx + c];
    }

    const int ntiles = (B_ * T_) / 64;   // 4096
    for (int tile = blockIdx.x; tile < ntiles; tile += gridDim.x) {
        __syncthreads();
        const int rbase = tile * 64;
        for (int idx = tid; idx < 64 * DI_; idx += 256) {
            int r = idx / DI_;
            int i = idx - r * DI_;
            in_s[i * INS_STRIDE + r] = inp[(size_t)(rbase + r) * DI_ + i];
        }
        __syncthreads();

        if (tx < 25) {
            ull acc[4][4];
#pragma unroll
            for (int p = 0; p < 4; p++)
#pragma unroll
                for (int c = 0; c < 4; c++) acc[p][c] = dup2(bv[c]);

#pragma unroll 4
            for (int i = 0; i < DI_; i++) {
                ulonglong2 ap0 = *(const ulonglong2*)(in_s + i * INS_STRIDE + 8 * ty);
                ulonglong2 ap1 = *(const ulonglong2*)(in_s + i * INS_STRIDE + 8 * ty + 4);
                float4 wv = *(const float4*)(Wx_s + i * H_ + 4 * tx);
                ull w0 = dup2(wv.x), w1 = dup2(wv.y), w2 = dup2(wv.z), w3 = dup2(wv.w);
                acc[0][0] = fma2(ap0.x, w0, acc[0][0]);
                acc[0][1] = fma2(ap0.x, w1, acc[0][1]);
                acc[0][2] = fma2(ap0.x, w2, acc[0][2]);
                acc[0][3] = fma2(ap0.x, w3, acc[0][3]);
                acc[1][0] = fma2(ap0.y, w0, acc[1][0]);
                acc[1][1] = fma2(ap0.y, w1, acc[1][1]);
                acc[1][2] = fma2(ap0.y, w2, acc[1][2]);
                acc[1][3] = fma2(ap0.y, w3, acc[1][3]);
                acc[2][0] = fma2(ap1.x, w0, acc[2][0]);
                acc[2][1] = fma2(ap1.x, w1, acc[2][1]);
                acc[2][2] = fma2(ap1.x, w2, acc[2][2]);
                acc[2][3] = fma2(ap1.x, w3, acc[2][3]);
                acc[3][0] = fma2(ap1.y, w0, acc[3][0]);
                acc[3][1] = fma2(ap1.y, w1, acc[3][1]);
                acc[3][2] = fma2(ap1.y, w2, acc[3][2]);
                acc[3][3] = fma2(ap1.y, w3, acc[3][3]);
            }
#pragma unroll
            for (int p = 0; p < 4; p++) {
                float2 c0 = u2f(acc[p][0]);
                float2 c1 = u2f(acc[p][1]);
                float2 c2 = u2f(acc[p][2]);
                float2 c3 = u2f(acc[p][3]);
                int re = rbase + 8 * ty + 2 * p;
                float4 oe; oe.x = c0.x; oe.y = c1.x; oe.z = c2.x; oe.w = c3.x;
                float4 oo; oo.x = c0.y; oo.y = c1.y; oo.z = c2.y; oo.w = c3.y;
                *(float4*)(g_xp + (size_t)re * H_ + 4 * tx)       = oe;
                *(float4*)(g_xp + (size_t)(re + 1) * H_ + 4 * tx) = oo;
            }
        }
    }
}

// ---------------------------------------------------------------------------
// Kernel B: sequential scan — EXACT round-15 version (2 warps/chain,
// 2 rows/thread, 64-thread named barriers, occ 2, clock64 de-phase stagger,
// branched depth-2 register prefetch ring). Measured as part of 519.5us.
// ---------------------------------------------------------------------------
__global__ void __launch_bounds__(128, 2) scan_kernel(
    const float* __restrict__ noise,   // [B, T, H]
    const float* __restrict__ Wh,      // [H, H]
    const float* __restrict__ ah0,     // [H]
    float* __restrict__ hstore)        // [B, T, H]
{
    __shared__ __align__(16) float hs[2][2][104];   // [pair][buf][k]

    const int tid  = threadIdx.x;
    const int lane = tid & 31;
    const int wp   = (tid >> 5) & 1;    // warp within pair
    const int pair = tid >> 6;          // 0 or 1
    const bool act = lane < 25;
    const int j0   = 50 * wp + lane;
    const int j1   = j0 + 25;
    const int chain = blockIdx.x * 2 + pair;
    const int barid = pair + 1;         // named barriers 1 and 2

    // de-phase co-resident CTAs (load-bearing: R16 ablation cost ~40us)
    {
        long long lim = (long long)((blockIdx.x & 1) * 300);
        long long s0 = clock64();
        while (clock64() - s0 < lim) {}
    }

    // 0.1*W rows j0, j1 packed over k (k-pairs)
    ull wk0[50], wk1[50];
    if (act) {
        const float2* w0 = (const float2*)(Wh + j0 * H_);
        const float2* w1 = (const float2*)(Wh + j1 * H_);
#pragma unroll
        for (int kk = 0; kk < 50; kk++) {
            float2 a = w0[kk];
            float2 b = w1[kk];
            wk0[kk] = pack2(0.1f * a.x, 0.1f * a.y);
            wk1[kk] = pack2(0.1f * b.x, 0.1f * b.y);
        }
    }

    float ahx = 0.f, ahy = 0.f;
    if (act) {
        ahx = ah0[j0];
        ahy = ah0[j1];
        hs[pair][0][j0] = tanhf(fmaxf(ahx, 0.f));
        hs[pair][0][j1] = tanhf(fmaxf(ahy, 0.f));
    }

    const size_t base = (size_t)chain * (T_ * H_);
    const float* xps = g_xp  + base + j0;    // row j1 = +25
    const float* nzs = noise + base + j0;
    float*       hst = hstore + base + j0;

    // depth-2 register prefetch ring
    float xc0 = 0.f, xc1 = 0.f, nc0 = 0.f, nc1 = 0.f;   // step t
    float xn0 = 0.f, xn1 = 0.f, nn0 = 0.f, nn1 = 0.f;   // step t+1
    if (act) {
        xc0 = xps[0];       xc1 = xps[25];
        nc0 = nzs[0];       nc1 = nzs[25];
        xn0 = xps[H_];      xn1 = xps[H_ + 25];
        nn0 = nzs[H_];      nn1 = nzs[H_ + 25];
    }
    __syncthreads();   // covers hs init for both pairs

    int buf = 0;
    for (int t = 0; t < T_; t++) {
        // prefetch t+2
        float p0 = 0.f, p1 = 0.f, q0 = 0.f, q1 = 0.f;
        if (act && t + 2 < T_) {
            size_t o = (size_t)(t + 2) * H_;
            p0 = xps[o];  p1 = xps[o + 25];
            q0 = nzs[o];  q1 = nzs[o + 25];
        }

        if (act) {
            const ulonglong2* h4 = (const ulonglong2*)hs[pair][buf];
            ull a0 = 0, b0 = 0, a1 = 0, b1 = 0;
#pragma unroll
            for (int kk = 0; kk < 25; kk++) {
                ulonglong2 v = h4[kk];            // k = 4kk .. 4kk+3
                a0 = fma2(v.x, wk0[2 * kk],     a0);
                b0 = fma2(v.y, wk0[2 * kk + 1], b0);
                a1 = fma2(v.x, wk1[2 * kk],     a1);
                b1 = fma2(v.y, wk1[2 * kk + 1], b1);
            }
            float2 s0 = u2f(add2(a0, b0));
            float2 s1 = u2f(add2(a1, b1));
            float sum0 = s0.x + s0.y;
            float sum1 = s1.x + s1.y;

            ahx = fmaf(0.9f, ahx, sum0 + xc0);
            ahy = fmaf(0.9f, ahy, sum1 + xc1);
            float x0 = fmaxf(ahx, 0.f);
            float x1 = fmaxf(ahy, 0.f);
            float e0 = __expf(-2.f * x0);
            float e1 = __expf(-2.f * x1);
            float h0 = __fdividef(1.f - e0, 1.f + e0) + nc0;
            float h1 = __fdividef(1.f - e1, 1.f + e1) + nc1;

            hs[pair][buf ^ 1][j0] = h0;
            hs[pair][buf ^ 1][j1] = h1;
            size_t o = (size_t)t * H_;
            hst[o]      = h0;
            hst[o + 25] = h1;
        }
        // rotate ring
        xc0 = xn0; xc1 = xn1; nc0 = nn0; nc1 = nn1;
        xn0 = p0;  xn1 = p1;  nn0 = q0;  nn1 = q1;
        buf ^= 1;
        asm volatile("bar.sync %0, %1;" :: "r"(barid), "r"(64) : "memory");
    }
}

// ---------------------------------------------------------------------------
// Kernel C: outproj, THREAD-PER-ROW, 256-thread blocks (round-14 shape),
// ONE change vs round-15 best: __ldcs streaming loads (hstore is a 105MB
// single-pass stream with zero reuse -> evict-first).
// ---------------------------------------------------------------------------
__global__ void __launch_bounds__(256) outproj_kernel(
    const float* __restrict__ hst,   // [B*T, H]
    const float* __restrict__ Wy,    // [DO, H]
    float* __restrict__ out)         // [B*T, DO]
{
    __shared__ ull wy2[H_];
    const int tid = threadIdx.x;
    if (tid < H_) wy2[tid] = pack2(Wy[tid], Wy[H_ + tid]);
    __syncthreads();

    const size_t row = (size_t)blockIdx.x * 256 + tid;
    const float4* rp = (const float4*)(hst + row * H_);   // 400B rows, 16B aligned

    ull acc0 = 0, acc1 = 0, acc2 = 0, acc3 = 0;
#pragma unroll
    for (int q = 0; q < 25; q++) {
        float4 v = __ldcs(rp + q);          // streaming: evict-first
        acc0 = fma2(dup2(v.x), wy2[4 * q + 0], acc0);
        acc1 = fma2(dup2(v.y), wy2[4 * q + 1], acc1);
        acc2 = fma2(dup2(v.z), wy2[4 * q + 2], acc2);
        acc3 = fma2(dup2(v.w), wy2[4 * q + 3], acc3);
    }
    ull r = add2(add2(acc0, acc1), add2(acc2, acc3));
    *(ull*)(out + row * DO_) = r;
}

// ---------------------------------------------------------------------------
extern "C" void kernel_launch(void* const* d_in, const int* in_sizes, int n_in,
                              void* d_out, int out_size)
{
    const float* inp   = (const float*)d_in[0];  // [B,T,DI]
    const float* noise = (const float*)d_in[1];  // [B,T,H]
    const float* Wx    = (const float*)d_in[2];  // [H,DI]
    const float* bias  = (const float*)d_in[3];  // [H]
    const float* Wh    = (const float*)d_in[4];  // [H,H]
    const float* Wy    = (const float*)d_in[5];  // [DO,H]
    const float* ah0   = (const float*)d_in[6];  // [H]

    float* out    = (float*)d_out;                  // [B,T,DO] first
    float* hstore = out + (size_t)B_ * T_ * DO_;    // [B,T,H] second

    const int xp_smem = (DI_ * H_ + DI_ * INS_STRIDE) * (int)sizeof(float);  // 67872 B
    static int attr_done = 0;
    if (!attr_done) {
        cudaFuncSetAttribute(xp_gemm_kernel,
                             cudaFuncAttributeMaxDynamicSharedMemorySize, xp_smem);
        cudaFuncSetAttribute(xp_gemm_kernel,
                             cudaFuncAttributePreferredSharedMemoryCarveout,
                             cudaSharedmemCarveoutMaxShared);
        attr_done = 1;
    }

    xp_gemm_kernel<<<1024, 256, xp_smem>>>(inp, Wx, bias);
    scan_kernel<<<B_ / 2, 128>>>(noise, Wh, ah0, hstore);
    outproj_kernel<<<(B_ * T_) / 256, 256>>>(hstore, Wy, out);
}